// round 14
// baseline (speedup 1.0000x reference)
#include <cuda_runtime.h>
#include <cstdint>

#define BATCH 64
#define TLEN  512
#define D     1024

// ---------------- scratch (device globals: no allocations allowed) ----------------
__device__ float g_ext[(size_t)TLEN * BATCH * D];   // 128 MB, layout [t][b][o]
__device__ float g_sbuf[2][BATCH * D];              // ping-pong: state + ext[t] combined
__device__ unsigned g_hbar[8 * 32];                  // [m-group][k-half] counters, 128B apart

typedef unsigned long long ULL;

// ---------------- packed f32x2 helpers (sm_103a FFMA2 path) ----------------
static __device__ __forceinline__ ULL pack_dup(float w) {
    ULL r;
    asm("mov.b64 %0, {%1, %1};" : "=l"(r) : "f"(w));
    return r;
}
static __device__ __forceinline__ ULL pack2(float lo, float hi) {
    ULL r;
    asm("mov.b64 %0, {%1, %2};" : "=l"(r) : "f"(lo), "f"(hi));
    return r;
}
static __device__ __forceinline__ void fma2(ULL& d, ULL a, ULL b) {
    asm("fma.rn.f32x2 %0, %1, %2, %0;" : "+l"(d) : "l"(a), "l"(b));
}
static __device__ __forceinline__ ULL addf2(ULL a, ULL b) {
    ULL r;
    asm("add.rn.f32x2 %0, %1, %2;" : "=l"(r) : "l"(a), "l"(b));
    return r;
}
static __device__ __forceinline__ void unpack2(ULL v, float& lo, float& hi) {
    asm("mov.b64 {%0, %1}, %2;" : "=f"(lo), "=f"(hi) : "l"(v));
}
static __device__ __forceinline__ uint32_t smem_u32(const void* p) {
    uint32_t a;
    asm("{ .reg .u64 t; cvta.to.shared.u64 t, %1; cvt.u32.u64 %0, t; }" : "=r"(a) : "l"(p));
    return a;
}

// ---------------- trivial zero kernels ----------------
__global__ void zero4_kernel(float4* __restrict__ p, int n4) {
    int i = blockIdx.x * blockDim.x + threadIdx.x;
    if (i < n4) p[i] = make_float4(0.f, 0.f, 0.f, 0.f);
}
__global__ void zero_misc_kernel() {
    int i = blockIdx.x * blockDim.x + threadIdx.x;
    if (i < 8 * 32) g_hbar[i] = 0u;
}

// ---------------- Phase A: ext[t][b][o] = sum_k x[m][k] * W_in[o][k], m=b*512+t --------
#define BM 128
#define BN 64
#define BK 32
#define PADA 134
#define PADB 68
#define ASTRIDE (BK * PADA)
#define BSTRIDE (BK * PADB)
#define EXT_SMEM ((2 * ASTRIDE + 2 * BSTRIDE) * 4)   // 51712 B

__global__ __launch_bounds__(256, 2) void ext_gemm_kernel(const float* __restrict__ X,
                                                          const float* __restrict__ Win) {
    extern __shared__ float esm[];
    float* As = esm;
    float* Bs = esm + 2 * ASTRIDE;

    const int tid = threadIdx.x;
    const int Mb = blockIdx.y * BM;
    const int Nb = blockIdx.x * BN;
    const int ty = tid >> 4, tx = tid & 15;
    const int m0 = ty * 8, n0 = tx * 4;

    ULL acc[4][4];
#pragma unroll
    for (int i = 0; i < 4; ++i)
#pragma unroll
        for (int j = 0; j < 4; ++j) acc[i][j] = 0ULL;

    const int ar = tid >> 3, ac = tid & 7;
    const int br = tid >> 2, bc = tid & 3;

    float4 ra[4], rb[2];
#pragma unroll
    for (int g = 0; g < 4; ++g)
        ra[g] = *(const float4*)&X[(size_t)(Mb + ar + g * 32) * D + ac * 4];
#pragma unroll
    for (int g = 0; g < 2; ++g)
        rb[g] = *(const float4*)&Win[(size_t)(Nb + br) * D + (bc + g * 4) * 4];
    {
#pragma unroll
        for (int g = 0; g < 4; ++g) {
            const int m = ar + g * 32;
            As[(ac * 4 + 0) * PADA + m] = ra[g].x;
            As[(ac * 4 + 1) * PADA + m] = ra[g].y;
            As[(ac * 4 + 2) * PADA + m] = ra[g].z;
            As[(ac * 4 + 3) * PADA + m] = ra[g].w;
        }
#pragma unroll
        for (int g = 0; g < 2; ++g) {
            const int cc = bc + g * 4;
            Bs[(cc * 4 + 0) * PADB + br] = rb[g].x;
            Bs[(cc * 4 + 1) * PADB + br] = rb[g].y;
            Bs[(cc * 4 + 2) * PADB + br] = rb[g].z;
            Bs[(cc * 4 + 3) * PADB + br] = rb[g].w;
        }
    }
    __syncthreads();

    for (int kt = 0; kt < D / BK; ++kt) {
        const int s = kt & 1;
        const float* Ac = As + s * ASTRIDE;
        const float* Bc = Bs + s * BSTRIDE;

        if (kt < D / BK - 1) {
            const int k0 = (kt + 1) * BK;
#pragma unroll
            for (int g = 0; g < 4; ++g)
                ra[g] = *(const float4*)&X[(size_t)(Mb + ar + g * 32) * D + k0 + ac * 4];
#pragma unroll
            for (int g = 0; g < 2; ++g)
                rb[g] = *(const float4*)&Win[(size_t)(Nb + br) * D + k0 + (bc + g * 4) * 4];
        }

#pragma unroll
        for (int kk = 0; kk < BK; ++kk) {
            const float* asr = &Ac[kk * PADA + m0];
            ULL a0 = *(const ULL*)(asr + 0);
            ULL a1 = *(const ULL*)(asr + 2);
            ULL a2 = *(const ULL*)(asr + 4);
            ULL a3 = *(const ULL*)(asr + 6);
            float4 bv = *(const float4*)&Bc[kk * PADB + n0];
            ULL b0 = pack_dup(bv.x);
            ULL b1 = pack_dup(bv.y);
            ULL b2 = pack_dup(bv.z);
            ULL b3 = pack_dup(bv.w);
            fma2(acc[0][0], a0, b0); fma2(acc[0][1], a0, b1); fma2(acc[0][2], a0, b2); fma2(acc[0][3], a0, b3);
            fma2(acc[1][0], a1, b0); fma2(acc[1][1], a1, b1); fma2(acc[1][2], a1, b2); fma2(acc[1][3], a1, b3);
            fma2(acc[2][0], a2, b0); fma2(acc[2][1], a2, b1); fma2(acc[2][2], a2, b2); fma2(acc[2][3], a2, b3);
            fma2(acc[3][0], a3, b0); fma2(acc[3][1], a3, b1); fma2(acc[3][2], a3, b2); fma2(acc[3][3], a3, b3);
        }

        if (kt < D / BK - 1) {
            float* An = As + (s ^ 1) * ASTRIDE;
            float* Bn = Bs + (s ^ 1) * BSTRIDE;
#pragma unroll
            for (int g = 0; g < 4; ++g) {
                const int m = ar + g * 32;
                An[(ac * 4 + 0) * PADA + m] = ra[g].x;
                An[(ac * 4 + 1) * PADA + m] = ra[g].y;
                An[(ac * 4 + 2) * PADA + m] = ra[g].z;
                An[(ac * 4 + 3) * PADA + m] = ra[g].w;
            }
#pragma unroll
            for (int g = 0; g < 2; ++g) {
                const int cc = bc + g * 4;
                Bn[(cc * 4 + 0) * PADB + br] = rb[g].x;
                Bn[(cc * 4 + 1) * PADB + br] = rb[g].y;
                Bn[(cc * 4 + 2) * PADB + br] = rb[g].z;
                Bn[(cc * 4 + 3) * PADB + br] = rb[g].w;
            }
        }
        __syncthreads();
    }

#pragma unroll
    for (int i = 0; i < 4; ++i) {
        float lo[4], hi[4];
#pragma unroll
        for (int j = 0; j < 4; ++j) unpack2(acc[i][j], lo[j], hi[j]);
        const int m = Mb + m0 + 2 * i;
        const int b0i = m >> 9, t0i = m & 511;
        const int b1i = (m + 1) >> 9, t1i = (m + 1) & 511;
        *(float4*)&g_ext[((size_t)t0i * BATCH + b0i) * D + Nb + n0] = make_float4(lo[0], lo[1], lo[2], lo[3]);
        *(float4*)&g_ext[((size_t)t1i * BATCH + b1i) * D + Nb + n0] = make_float4(hi[0], hi[1], hi[2], hi[3]);
    }
}

// ---------------- Phase B: persistent recurrence, reduce-free + half-pipelined ----------
// 256 threads, 8 warps. Warp w owns n-cols [4w, 4w+4) over FULL k=1024 (64 outputs/warp,
// perfectly balanced) -> NO cross-warp reduction. Lane = (ml 0..7, nc 0..3): outputs
// (ml, 4w+nc) and (ml+8, 4w+nc), k-pair-packed accs; inner 4k: 2 a-LDS.128 (conflict-
// free: row bank-shift 4) + 1 w-LDS.128 + 4 FFMA2, no MOVs.
// Dataflow: producers signal per-(m-group, k-half) counters (16 CTAs each). Warp 7
// lanes 0/1 poll the two halves in parallel and bulk-copy 16 x 2KB per half into sT
// (two mbarriers). All warps compute half 0 while half 1 arrives.
#define NTILE 32
#define MTILE 16
#define WROW 514                              // ULLs per WTk row (512 + 2 pad)
#define WT_ULL (NTILE * WROW)                 // 16448 ULL = 131584 B
#define ST_STRIDE 1028
#define ST_FLOATS (MTILE * ST_STRIDE)         // 16448 floats = 65792 B
#define OFF_MBAR (WT_ULL * 8 + ST_FLOATS * 4)
#define PERS_SMEM (OFF_MBAR + 32)             // 197440 B

__global__ __launch_bounds__(256, 1) void rnn_persistent(const float* __restrict__ Wr) {
    extern __shared__ char smc[];
    ULL*   WTk = (ULL*)smc;                   // [32 n][514] k-pair-packed W
    float* sT  = (float*)(smc + WT_ULL * 8);  // [16 m][1028]

    const int tid  = threadIdx.x;
    const int w    = tid >> 5;
    const int lane = tid & 31;
    const int ml   = lane & 7;                // m rows ml, ml+8
    const int nc   = lane >> 3;               // n = 4w + nc
    const int Nb = blockIdx.x * NTILE;
    const int Mb = blockIdx.y * MTILE;

    const uint32_t mbar0 = smem_u32(smc) + OFF_MBAR;   // mbar h=0 at +0, h=1 at +8
    const uint32_t sT_a  = smem_u32(sT);

    const int ng = Nb + 4 * w + nc;           // this lane's global n
    unsigned* sigc = &g_hbar[(blockIdx.y * 2 + (blockIdx.x >> 4)) * 32];

    // ---- stage WTk[n][k-pairs] once (k-pair-packed ULLs) ----
    {
        const int n = tid >> 3, c = tid & 7;  // n row, 128-float chunk c
        const float* wp = Wr + (size_t)(Nb + n) * D + c * 128;
        ULL* dst = WTk + (size_t)n * WROW + c * 64;
#pragma unroll
        for (int j = 0; j < 32; ++j) {
            float4 v = __ldg((const float4*)(wp + 4 * j));
            dst[2 * j]     = pack2(v.x, v.y);
            dst[2 * j + 1] = pack2(v.z, v.w);
        }
    }
    if (tid < 2) {
        asm volatile("mbarrier.init.shared.b64 [%0], %1;"
                     :: "r"(mbar0 + 8u * (uint32_t)tid), "r"(1) : "memory");
    }
    __syncthreads();

    for (int t = 0; t < TLEN; ++t) {
        // ---- prefetch ext[t+1] for this lane's 2 outputs ----
        float e0 = 0.f, e1 = 0.f;
        if (t + 1 < TLEN) {
            const float* eb = g_ext + (size_t)(t + 1) * (BATCH * D);
            e0 = __ldg(&eb[(size_t)(Mb + ml) * D + ng]);
            e1 = __ldg(&eb[(size_t)(Mb + ml + 8) * D + ng]);
        }

        // ---- agents: warp 7 lanes 0/1 poll + copy their k-half in parallel ----
        if (w == 7 && lane < 2) {
            const int h = lane;
            unsigned* ctr = &g_hbar[(blockIdx.y * 2 + h) * 32];
            if (t > 0) {
                const unsigned target = 16u * (unsigned)t;
                unsigned v;
                do {
                    asm volatile("ld.acquire.gpu.u32 %0, [%1];" : "=r"(v) : "l"(ctr));
                } while (v < target);
            }
            const float* src = ((t == 0) ? (g_ext + (size_t)Mb * D)
                                         : (g_sbuf[t & 1] + (size_t)Mb * D)) + h * 512;
            const uint32_t mb = mbar0 + 8u * (uint32_t)h;
            asm volatile("mbarrier.arrive.expect_tx.shared.b64 _, [%0], %1;"
                         :: "r"(mb), "r"(32768) : "memory");
#pragma unroll
            for (int m = 0; m < MTILE; ++m) {
                asm volatile("cp.async.bulk.shared::cta.global.mbarrier::complete_tx::bytes [%0], [%1], %2, [%3];"
                             :: "r"(sT_a + (uint32_t)(m * ST_STRIDE + h * 512) * 4u),
                                "l"(src + (size_t)m * D), "r"(2048), "r"(mb) : "memory");
            }
        }

        // ---- compute both halves as they arrive; accs persist across halves ----
        ULL c00 = 0ULL, c01 = 0ULL, c10 = 0ULL, c11 = 0ULL;
        const ULL* wrow = WTk + (size_t)(4 * w + nc) * WROW;

#pragma unroll
        for (int h = 0; h < 2; ++h) {
            // wait for half h (HW-sleep try_wait; parity = t&1)
            {
                const uint32_t mb = mbar0 + 8u * (uint32_t)h;
                const uint32_t parity = (uint32_t)(t & 1);
                uint32_t done;
                do {
                    asm volatile(
                        "{\n\t.reg .pred p;\n\t"
                        "mbarrier.try_wait.parity.acquire.cta.shared::cta.b64 p, [%1], %2, 0x989680;\n\t"
                        "selp.b32 %0, 1, 0, p;\n\t}"
                        : "=r"(done) : "r"(mb), "r"(parity) : "memory");
                } while (!done);
            }

            const float* a0p = sT + (size_t)ml * ST_STRIDE + h * 512;
            const float* a1p = a0p + 8 * ST_STRIDE;
            const ULL* wv = wrow + h * 256;
#pragma unroll 8
            for (int i = 0; i < 128; ++i) {
                ulonglong2 av0 = *(const ulonglong2*)(a0p + 4 * i);
                ulonglong2 av1 = *(const ulonglong2*)(a1p + 4 * i);
                ulonglong2 wv2 = *(const ulonglong2*)(wv + 2 * i);
                fma2(c00, av0.x, wv2.x); fma2(c01, av0.y, wv2.y);
                fma2(c10, av1.x, wv2.x); fma2(c11, av1.y, wv2.y);
            }
        }

        // ---- epilogue: fold k-parity, ReLU, fuse ext[t+1], write combined buffer ----
        {
            float* sout = g_sbuf[(t + 1) & 1];
            float lo, hi;
            unpack2(addf2(c00, c01), lo, hi);
            float v0 = fmaxf(lo + hi, 0.f);
            unpack2(addf2(c10, c11), lo, hi);
            float v1 = fmaxf(lo + hi, 0.f);
            if (t + 1 < TLEN) { v0 += e0; v1 += e1; }
            __stcg(&sout[(size_t)(Mb + ml) * D + ng], v0);
            __stcg(&sout[(size_t)(Mb + ml + 8) * D + ng], v1);
        }
        __syncthreads();   // all sT reads + STGs done before signal / next copies

        if (tid == 0) {
            __threadfence();
            atomicAdd(sigc, 1u);
        }
    }
}

// ---------------- final: out[:,0,:] = final state (g_sbuf[0], TLEN even) ----------------
__global__ void final_copy_kernel(float* __restrict__ out) {
    const int i = blockIdx.x * blockDim.x + threadIdx.x;   // < 65536
    const int b = i >> 10, o = i & 1023;
    out[(size_t)b * (TLEN * D) + o] = g_sbuf[0][i];
}

// ---------------- launch ----------------
extern "C" void kernel_launch(void* const* d_in, const int* in_sizes, int n_in,
                              void* d_out, int out_size) {
    const float* x     = (const float*)d_in[0];
    const float* W_in  = (const float*)d_in[1];
    const float* W_rec = (const float*)d_in[2];
    float* out = (float*)d_out;

    cudaFuncSetAttribute(rnn_persistent, cudaFuncAttributeMaxDynamicSharedMemorySize, PERS_SMEM);
    cudaFuncSetAttribute(ext_gemm_kernel, cudaFuncAttributeMaxDynamicSharedMemorySize, EXT_SMEM);

    // zero output (poisoned by harness) + dataflow counters
    zero4_kernel<<<(BATCH * TLEN * D / 4 + 255) / 256, 256>>>((float4*)out, BATCH * TLEN * D / 4);
    zero_misc_kernel<<<1, 256>>>();

    // Phase A: input projections for all timesteps (ext layout [t][b][o])
    ext_gemm_kernel<<<dim3(D / BN, (BATCH * TLEN) / BM), 256, EXT_SMEM>>>(x, W_in);

    // Phase B: full recurrence in one persistent kernel
    rnn_persistent<<<dim3(D / NTILE, BATCH / MTILE), 256, PERS_SMEM>>>(W_rec);

    // write final state into out[:,0,:]
    final_copy_kernel<<<(BATCH * D) / 256, 256>>>(out);
}

// round 15
// speedup vs baseline: 1.5006x; 1.5006x over previous
#include <cuda_runtime.h>
#include <cstdint>

#define BATCH 64
#define TLEN  512
#define D     1024

// ---------------- scratch (device globals: no allocations allowed) ----------------
__device__ float g_ext[(size_t)TLEN * BATCH * D];   // 128 MB, layout [t][b][o]
__device__ float g_sbuf[2][BATCH * D];              // ping-pong: state + ext[t] combined
__device__ unsigned g_hbar[8 * 32];                  // [m-group][m-half] counters, 128B apart

typedef unsigned long long ULL;

// ---------------- packed f32x2 helpers (sm_103a FFMA2 path) ----------------
static __device__ __forceinline__ ULL pack_dup(float w) {
    ULL r;
    asm("mov.b64 %0, {%1, %1};" : "=l"(r) : "f"(w));
    return r;
}
static __device__ __forceinline__ void fma2(ULL& d, ULL a, ULL b) {
    asm("fma.rn.f32x2 %0, %1, %2, %0;" : "+l"(d) : "l"(a), "l"(b));
}
static __device__ __forceinline__ void unpack2(ULL v, float& lo, float& hi) {
    asm("mov.b64 {%0, %1}, %2;" : "=f"(lo), "=f"(hi) : "l"(v));
}
static __device__ __forceinline__ uint32_t smem_u32(const void* p) {
    uint32_t a;
    asm("{ .reg .u64 t; cvta.to.shared.u64 t, %1; cvt.u32.u64 %0, t; }" : "=r"(a) : "l"(p));
    return a;
}

// ---------------- trivial zero kernels ----------------
__global__ void zero4_kernel(float4* __restrict__ p, int n4) {
    int i = blockIdx.x * blockDim.x + threadIdx.x;
    if (i < n4) p[i] = make_float4(0.f, 0.f, 0.f, 0.f);
}
__global__ void zero_misc_kernel() {
    int i = blockIdx.x * blockDim.x + threadIdx.x;
    if (i < 8 * 32) g_hbar[i] = 0u;
}

// ---------------- Phase A: ext[t][b][o] = sum_k x[m][k] * W_in[o][k], m=b*512+t --------
#define BM 128
#define BN 64
#define BK 32
#define PADA 134
#define PADB 68
#define ASTRIDE (BK * PADA)
#define BSTRIDE (BK * PADB)
#define EXT_SMEM ((2 * ASTRIDE + 2 * BSTRIDE) * 4)   // 51712 B

__global__ __launch_bounds__(256, 2) void ext_gemm_kernel(const float* __restrict__ X,
                                                          const float* __restrict__ Win) {
    extern __shared__ float esm[];
    float* As = esm;
    float* Bs = esm + 2 * ASTRIDE;

    const int tid = threadIdx.x;
    const int Mb = blockIdx.y * BM;
    const int Nb = blockIdx.x * BN;
    const int ty = tid >> 4, tx = tid & 15;
    const int m0 = ty * 8, n0 = tx * 4;

    ULL acc[4][4];
#pragma unroll
    for (int i = 0; i < 4; ++i)
#pragma unroll
        for (int j = 0; j < 4; ++j) acc[i][j] = 0ULL;

    const int ar = tid >> 3, ac = tid & 7;
    const int br = tid >> 2, bc = tid & 3;

    float4 ra[4], rb[2];
#pragma unroll
    for (int g = 0; g < 4; ++g)
        ra[g] = *(const float4*)&X[(size_t)(Mb + ar + g * 32) * D + ac * 4];
#pragma unroll
    for (int g = 0; g < 2; ++g)
        rb[g] = *(const float4*)&Win[(size_t)(Nb + br) * D + (bc + g * 4) * 4];
    {
#pragma unroll
        for (int g = 0; g < 4; ++g) {
            const int m = ar + g * 32;
            As[(ac * 4 + 0) * PADA + m] = ra[g].x;
            As[(ac * 4 + 1) * PADA + m] = ra[g].y;
            As[(ac * 4 + 2) * PADA + m] = ra[g].z;
            As[(ac * 4 + 3) * PADA + m] = ra[g].w;
        }
#pragma unroll
        for (int g = 0; g < 2; ++g) {
            const int cc = bc + g * 4;
            Bs[(cc * 4 + 0) * PADB + br] = rb[g].x;
            Bs[(cc * 4 + 1) * PADB + br] = rb[g].y;
            Bs[(cc * 4 + 2) * PADB + br] = rb[g].z;
            Bs[(cc * 4 + 3) * PADB + br] = rb[g].w;
        }
    }
    __syncthreads();

    for (int kt = 0; kt < D / BK; ++kt) {
        const int s = kt & 1;
        const float* Ac = As + s * ASTRIDE;
        const float* Bc = Bs + s * BSTRIDE;

        if (kt < D / BK - 1) {
            const int k0 = (kt + 1) * BK;
#pragma unroll
            for (int g = 0; g < 4; ++g)
                ra[g] = *(const float4*)&X[(size_t)(Mb + ar + g * 32) * D + k0 + ac * 4];
#pragma unroll
            for (int g = 0; g < 2; ++g)
                rb[g] = *(const float4*)&Win[(size_t)(Nb + br) * D + k0 + (bc + g * 4) * 4];
        }

#pragma unroll
        for (int kk = 0; kk < BK; ++kk) {
            const float* asr = &Ac[kk * PADA + m0];
            ULL a0 = *(const ULL*)(asr + 0);
            ULL a1 = *(const ULL*)(asr + 2);
            ULL a2 = *(const ULL*)(asr + 4);
            ULL a3 = *(const ULL*)(asr + 6);
            float4 bv = *(const float4*)&Bc[kk * PADB + n0];
            ULL b0 = pack_dup(bv.x);
            ULL b1 = pack_dup(bv.y);
            ULL b2 = pack_dup(bv.z);
            ULL b3 = pack_dup(bv.w);
            fma2(acc[0][0], a0, b0); fma2(acc[0][1], a0, b1); fma2(acc[0][2], a0, b2); fma2(acc[0][3], a0, b3);
            fma2(acc[1][0], a1, b0); fma2(acc[1][1], a1, b1); fma2(acc[1][2], a1, b2); fma2(acc[1][3], a1, b3);
            fma2(acc[2][0], a2, b0); fma2(acc[2][1], a2, b1); fma2(acc[2][2], a2, b2); fma2(acc[2][3], a2, b3);
            fma2(acc[3][0], a3, b0); fma2(acc[3][1], a3, b1); fma2(acc[3][2], a3, b2); fma2(acc[3][3], a3, b3);
        }

        if (kt < D / BK - 1) {
            float* An = As + (s ^ 1) * ASTRIDE;
            float* Bn = Bs + (s ^ 1) * BSTRIDE;
#pragma unroll
            for (int g = 0; g < 4; ++g) {
                const int m = ar + g * 32;
                An[(ac * 4 + 0) * PADA + m] = ra[g].x;
                An[(ac * 4 + 1) * PADA + m] = ra[g].y;
                An[(ac * 4 + 2) * PADA + m] = ra[g].z;
                An[(ac * 4 + 3) * PADA + m] = ra[g].w;
            }
#pragma unroll
            for (int g = 0; g < 2; ++g) {
                const int cc = bc + g * 4;
                Bn[(cc * 4 + 0) * PADB + br] = rb[g].x;
                Bn[(cc * 4 + 1) * PADB + br] = rb[g].y;
                Bn[(cc * 4 + 2) * PADB + br] = rb[g].z;
                Bn[(cc * 4 + 3) * PADB + br] = rb[g].w;
            }
        }
        __syncthreads();
    }

#pragma unroll
    for (int i = 0; i < 4; ++i) {
        float lo[4], hi[4];
#pragma unroll
        for (int j = 0; j < 4; ++j) unpack2(acc[i][j], lo[j], hi[j]);
        const int m = Mb + m0 + 2 * i;
        const int b0i = m >> 9, t0i = m & 511;
        const int b1i = (m + 1) >> 9, t1i = (m + 1) & 511;
        *(float4*)&g_ext[((size_t)t0i * BATCH + b0i) * D + Nb + n0] = make_float4(lo[0], lo[1], lo[2], lo[3]);
        *(float4*)&g_ext[((size_t)t1i * BATCH + b1i) * D + Nb + n0] = make_float4(hi[0], hi[1], hi[2], hi[3]);
    }
}

// ---------------- Phase B: persistent recurrence, independent m-half pipeline ----------
// Row m of the output depends ONLY on row m of the input -> the 16-row m-group splits
// into two independent 8-row sub-recurrences. CTA alternates halves: iteration i
// handles (t = i>>1, h = i&1). While computing half h, the bulk copy for half h of
// step t+1 is already in flight (tid0 signals its epilogue, polls the 32-producer
// counter — typically complete one half-iteration ago — and issues the next copy).
// Compute per half: warp = 128-k slice, lane = (mg 0..3, ng 0..7) -> rows {mg, mg+4},
// n cols [4ng, 4ng+4) as 2 n-pair-packed accs per row. Per 4k: 6 conflict-free LDS +
// 8 dup-MOV + 16 FFMA2 (fma-pipe bound, 2048 cyc/half/SM).
#define NTILE 32
#define MTILE 16
#define HROWS 8
#define WT_STRIDE 36
#define WT_FLOATS (D * WT_STRIDE)            // 36864
#define ST_H (HROWS * 1028)                  // 8224 floats per half buffer
#define ST_FLOATS (2 * ST_H)                 // 16448
#define REDH 288                             // 8 rows * 36
#define RED_FLOATS (8 * REDH)                // 2304
#define OFF_MBAR ((WT_FLOATS + ST_FLOATS + RED_FLOATS) * 4)
#define PERS_SMEM (OFF_MBAR + 16)            // 222480 B

__global__ __launch_bounds__(256, 1) void rnn_persistent(const float* __restrict__ Wr) {
    extern __shared__ float sm[];
    float* WT  = sm;                          // [1024 k][36]
    float* sT  = sm + WT_FLOATS;              // two half-buffers [8][1028]
    float* red = sm + WT_FLOATS + ST_FLOATS;  // [8 w][8 m * 36]

    const int tid  = threadIdx.x;
    const int w    = tid >> 5;
    const int lane = tid & 31;
    const int mg   = lane >> 3;               // 0..3: rows mg, mg+4 within half
    const int ng   = lane & 7;                // n cols [4ng, 4ng+4)
    const int Nb = blockIdx.x * NTILE;
    const int Mb = blockIdx.y * MTILE;

    const uint32_t mbar0 = smem_u32(sm) + OFF_MBAR;   // mbar[h] at +8h
    const uint32_t sT_a  = smem_u32(sT);

    // reduce/epilogue mapping: 1 output per thread
    const int om = tid >> 5, on = tid & 31;

    // ---- stage WT[k][n] once (transposed W slice) ----
    {
        const int n = tid & 31, kc = tid >> 5;
        const float* wp = Wr + (size_t)(Nb + n) * D + kc * 128;
        float* wt = WT + (size_t)(kc * 128) * WT_STRIDE + n;
#pragma unroll
        for (int j = 0; j < 32; ++j) {
            float4 v = __ldg((const float4*)(wp + 4 * j));
            float* dst = wt + (4 * j) * WT_STRIDE;
            dst[0] = v.x;
            dst[WT_STRIDE] = v.y;
            dst[2 * WT_STRIDE] = v.z;
            dst[3 * WT_STRIDE] = v.w;
        }
    }
    if (tid < 2) {
        asm volatile("mbarrier.init.shared.b64 [%0], %1;"
                     :: "r"(mbar0 + 8u * (uint32_t)tid), "r"(1) : "memory");
    }
    __syncthreads();

    // ---- prologue: issue copies for both halves of step 0 (state0=0 -> ext[0]) ----
    if (tid == 0) {
#pragma unroll
        for (int h = 0; h < 2; ++h) {
            const float* src = g_ext + (size_t)(Mb + 8 * h) * D;
            const uint32_t mb = mbar0 + 8u * (uint32_t)h;
            asm volatile("mbarrier.arrive.expect_tx.shared.b64 _, [%0], %1;"
                         :: "r"(mb), "r"(32768) : "memory");
#pragma unroll
            for (int m = 0; m < HROWS; ++m) {
                asm volatile("cp.async.bulk.shared::cta.global.mbarrier::complete_tx::bytes [%0], [%1], %2, [%3];"
                             :: "r"(sT_a + (uint32_t)((h * ST_H + m * 1028) * 4)),
                                "l"(src + (size_t)m * D), "r"(4096), "r"(mb) : "memory");
            }
        }
    }

    for (int i = 0; i < 2 * TLEN; ++i) {
        const int t = i >> 1, h = i & 1;

        // ---- prefetch ext[t+1] for this thread's output (hidden by compute) ----
        float e = 0.f;
        if (t + 1 < TLEN)
            e = __ldg(&g_ext[(size_t)(t + 1) * (BATCH * D) + (size_t)(Mb + 8 * h + om) * D + Nb + on]);

        // ---- wait for this half's input tile (copy issued 2 iterations ago) ----
        {
            const uint32_t mb = mbar0 + 8u * (uint32_t)h;
            const uint32_t parity = (uint32_t)(t & 1);
            uint32_t done;
            do {
                asm volatile(
                    "{\n\t.reg .pred p;\n\t"
                    "mbarrier.try_wait.parity.acquire.cta.shared::cta.b64 p, [%1], %2, 0x989680;\n\t"
                    "selp.b32 %0, 1, 0, p;\n\t}"
                    : "=r"(done) : "r"(mb), "r"(parity) : "memory");
            } while (!done);
        }

        // ---- compute: rows {mg, mg+4}, cols [4ng,4ng+4), this warp's 128-k slice ----
        ULL acc0 = 0ULL, acc1 = 0ULL, acc2 = 0ULL, acc3 = 0ULL;
        {
            const float* sTh = sT + h * ST_H;
            const float* a0p = sTh + (size_t)mg * 1028 + w * 128;
            const float* a1p = a0p + 4 * 1028;
            const float* wtp = WT + (size_t)(w * 128) * WT_STRIDE + 4 * ng;
#pragma unroll 8
            for (int q = 0; q < 32; ++q) {
                const int k = 4 * q;
                float4 av0 = *(const float4*)(a0p + k);
                float4 av1 = *(const float4*)(a1p + k);
                const float* wk = wtp + (size_t)k * WT_STRIDE;
                ulonglong2 w0 = *(const ulonglong2*)(wk);
                ulonglong2 w1 = *(const ulonglong2*)(wk + WT_STRIDE);
                ulonglong2 w2 = *(const ulonglong2*)(wk + 2 * WT_STRIDE);
                ulonglong2 w3 = *(const ulonglong2*)(wk + 3 * WT_STRIDE);
                ULL d;
                d = pack_dup(av0.x); fma2(acc0, d, w0.x); fma2(acc1, d, w0.y);
                d = pack_dup(av1.x); fma2(acc2, d, w0.x); fma2(acc3, d, w0.y);
                d = pack_dup(av0.y); fma2(acc0, d, w1.x); fma2(acc1, d, w1.y);
                d = pack_dup(av1.y); fma2(acc2, d, w1.x); fma2(acc3, d, w1.y);
                d = pack_dup(av0.z); fma2(acc0, d, w2.x); fma2(acc1, d, w2.y);
                d = pack_dup(av1.z); fma2(acc2, d, w2.x); fma2(acc3, d, w2.y);
                d = pack_dup(av0.w); fma2(acc0, d, w3.x); fma2(acc1, d, w3.y);
                d = pack_dup(av1.w); fma2(acc2, d, w3.x); fma2(acc3, d, w3.y);
            }
        }

        // ---- store per-warp partials (two 16B STS per lane) ----
        {
            float* rw = red + w * REDH + 4 * ng;
            ulonglong2 p0; p0.x = acc0; p0.y = acc1;
            ulonglong2 p1; p1.x = acc2; p1.y = acc3;
            *(ulonglong2*)(rw + mg * 36)       = p0;
            *(ulonglong2*)(rw + (mg + 4) * 36) = p1;
        }
        __syncthreads();

        // ---- reduce over 8 k-slices, ReLU, fuse ext[t+1], write combined buffer ----
        {
            float s = 0.f;
#pragma unroll
            for (int g = 0; g < 8; ++g) s += red[g * REDH + om * 36 + on];
            float v = fmaxf(s, 0.f);
            if (t + 1 < TLEN) v += e;
            __stcg(&g_sbuf[(t + 1) & 1][(size_t)(Mb + 8 * h + om) * D + Nb + on], v);
        }
        __syncthreads();   // all STGs + red reads done before signal / buffer reuse

        // ---- signal, then poll + issue next copy for this half (overlaps other half) ----
        if (tid == 0) {
            unsigned* ctr = &g_hbar[(blockIdx.y * 2 + h) * 32];
            __threadfence();
            atomicAdd(ctr, 1u);
            if (i + 2 < 2 * TLEN) {
                const unsigned target = 32u * (unsigned)(t + 1);
                unsigned vv;
                do {
                    asm volatile("ld.acquire.gpu.u32 %0, [%1];" : "=r"(vv) : "l"(ctr));
                } while (vv < target);
                const float* src = g_sbuf[(t + 1) & 1] + (size_t)(Mb + 8 * h) * D;
                const uint32_t mb = mbar0 + 8u * (uint32_t)h;
                asm volatile("mbarrier.arrive.expect_tx.shared.b64 _, [%0], %1;"
                             :: "r"(mb), "r"(32768) : "memory");
#pragma unroll
                for (int m = 0; m < HROWS; ++m) {
                    asm volatile("cp.async.bulk.shared::cta.global.mbarrier::complete_tx::bytes [%0], [%1], %2, [%3];"
                                 :: "r"(sT_a + (uint32_t)((h * ST_H + m * 1028) * 4)),
                                    "l"(src + (size_t)m * D), "r"(4096), "r"(mb) : "memory");
                }
            }
        }
    }
}

// ---------------- final: out[:,0,:] = final state (g_sbuf[0], TLEN even) ----------------
__global__ void final_copy_kernel(float* __restrict__ out) {
    const int i = blockIdx.x * blockDim.x + threadIdx.x;   // < 65536
    const int b = i >> 10, o = i & 1023;
    out[(size_t)b * (TLEN * D) + o] = g_sbuf[0][i];
}

// ---------------- launch ----------------
extern "C" void kernel_launch(void* const* d_in, const int* in_sizes, int n_in,
                              void* d_out, int out_size) {
    const float* x     = (const float*)d_in[0];
    const float* W_in  = (const float*)d_in[1];
    const float* W_rec = (const float*)d_in[2];
    float* out = (float*)d_out;

    cudaFuncSetAttribute(rnn_persistent, cudaFuncAttributeMaxDynamicSharedMemorySize, PERS_SMEM);
    cudaFuncSetAttribute(ext_gemm_kernel, cudaFuncAttributeMaxDynamicSharedMemorySize, EXT_SMEM);

    // zero output (poisoned by harness) + dataflow counters
    zero4_kernel<<<(BATCH * TLEN * D / 4 + 255) / 256, 256>>>((float4*)out, BATCH * TLEN * D / 4);
    zero_misc_kernel<<<1, 256>>>();

    // Phase A: input projections for all timesteps (ext layout [t][b][o])
    ext_gemm_kernel<<<dim3(D / BN, (BATCH * TLEN) / BM), 256, EXT_SMEM>>>(x, W_in);

    // Phase B: full recurrence in one persistent kernel
    rnn_persistent<<<dim3(D / NTILE, BATCH / MTILE), 256, PERS_SMEM>>>(W_rec);

    // write final state into out[:,0,:]
    final_copy_kernel<<<(BATCH * D) / 256, 256>>>(out);
}

// round 16
// speedup vs baseline: 1.8216x; 1.2139x over previous
#include <cuda_runtime.h>
#include <cstdint>

#define BATCH 64
#define TLEN  512
#define D     1024

// ---------------- scratch (device globals: no allocations allowed) ----------------
__device__ float g_ext[(size_t)TLEN * BATCH * D];   // 128 MB, layout [t][b][o]
__device__ float g_sbuf[2][BATCH * D];              // ping-pong: state + ext[t] combined
__device__ unsigned g_bars[4 * 32];                  // per-m-group barrier counters

typedef unsigned long long ULL;

// ---------------- packed f32x2 helpers (sm_103a FFMA2 path) ----------------
static __device__ __forceinline__ ULL pack_dup(float w) {
    ULL r;
    asm("mov.b64 %0, {%1, %1};" : "=l"(r) : "f"(w));
    return r;
}
static __device__ __forceinline__ void fma2(ULL& d, ULL a, ULL b) {
    asm("fma.rn.f32x2 %0, %1, %2, %0;" : "+l"(d) : "l"(a), "l"(b));
}
static __device__ __forceinline__ void unpack2(ULL v, float& lo, float& hi) {
    asm("mov.b64 {%0, %1}, %2;" : "=f"(lo), "=f"(hi) : "l"(v));
}
static __device__ __forceinline__ uint32_t smem_u32(const void* p) {
    uint32_t a;
    asm("{ .reg .u64 t; cvta.to.shared.u64 t, %1; cvt.u32.u64 %0, t; }" : "=r"(a) : "l"(p));
    return a;
}

// ---------------- trivial zero kernels ----------------
__global__ void zero4_kernel(float4* __restrict__ p, int n4) {
    int i = blockIdx.x * blockDim.x + threadIdx.x;
    if (i < n4) p[i] = make_float4(0.f, 0.f, 0.f, 0.f);
}
__global__ void zero_misc_kernel() {
    int i = blockIdx.x * blockDim.x + threadIdx.x;
    if (i < 4 * 32) g_bars[i] = 0u;
}

// ---------------- Phase A: ext[t][b][o] = sum_k x[m][k] * W_in[o][k], m=b*512+t --------
#define BM 128
#define BN 64
#define BK 32
#define PADA 134
#define PADB 68
#define ASTRIDE (BK * PADA)
#define BSTRIDE (BK * PADB)
#define EXT_SMEM ((2 * ASTRIDE + 2 * BSTRIDE) * 4)   // 51712 B

__global__ __launch_bounds__(256, 2) void ext_gemm_kernel(const float* __restrict__ X,
                                                          const float* __restrict__ Win) {
    extern __shared__ float esm[];
    float* As = esm;
    float* Bs = esm + 2 * ASTRIDE;

    const int tid = threadIdx.x;
    const int Mb = blockIdx.y * BM;
    const int Nb = blockIdx.x * BN;
    const int ty = tid >> 4, tx = tid & 15;
    const int m0 = ty * 8, n0 = tx * 4;

    ULL acc[4][4];
#pragma unroll
    for (int i = 0; i < 4; ++i)
#pragma unroll
        for (int j = 0; j < 4; ++j) acc[i][j] = 0ULL;

    const int ar = tid >> 3, ac = tid & 7;
    const int br = tid >> 2, bc = tid & 3;

    float4 ra[4], rb[2];
#pragma unroll
    for (int g = 0; g < 4; ++g)
        ra[g] = *(const float4*)&X[(size_t)(Mb + ar + g * 32) * D + ac * 4];
#pragma unroll
    for (int g = 0; g < 2; ++g)
        rb[g] = *(const float4*)&Win[(size_t)(Nb + br) * D + (bc + g * 4) * 4];
    {
#pragma unroll
        for (int g = 0; g < 4; ++g) {
            const int m = ar + g * 32;
            As[(ac * 4 + 0) * PADA + m] = ra[g].x;
            As[(ac * 4 + 1) * PADA + m] = ra[g].y;
            As[(ac * 4 + 2) * PADA + m] = ra[g].z;
            As[(ac * 4 + 3) * PADA + m] = ra[g].w;
        }
#pragma unroll
        for (int g = 0; g < 2; ++g) {
            const int cc = bc + g * 4;
            Bs[(cc * 4 + 0) * PADB + br] = rb[g].x;
            Bs[(cc * 4 + 1) * PADB + br] = rb[g].y;
            Bs[(cc * 4 + 2) * PADB + br] = rb[g].z;
            Bs[(cc * 4 + 3) * PADB + br] = rb[g].w;
        }
    }
    __syncthreads();

    for (int kt = 0; kt < D / BK; ++kt) {
        const int s = kt & 1;
        const float* Ac = As + s * ASTRIDE;
        const float* Bc = Bs + s * BSTRIDE;

        if (kt < D / BK - 1) {
            const int k0 = (kt + 1) * BK;
#pragma unroll
            for (int g = 0; g < 4; ++g)
                ra[g] = *(const float4*)&X[(size_t)(Mb + ar + g * 32) * D + k0 + ac * 4];
#pragma unroll
            for (int g = 0; g < 2; ++g)
                rb[g] = *(const float4*)&Win[(size_t)(Nb + br) * D + k0 + (bc + g * 4) * 4];
        }

#pragma unroll
        for (int kk = 0; kk < BK; ++kk) {
            const float* asr = &Ac[kk * PADA + m0];
            ULL a0 = *(const ULL*)(asr + 0);
            ULL a1 = *(const ULL*)(asr + 2);
            ULL a2 = *(const ULL*)(asr + 4);
            ULL a3 = *(const ULL*)(asr + 6);
            float4 bv = *(const float4*)&Bc[kk * PADB + n0];
            ULL b0 = pack_dup(bv.x);
            ULL b1 = pack_dup(bv.y);
            ULL b2 = pack_dup(bv.z);
            ULL b3 = pack_dup(bv.w);
            fma2(acc[0][0], a0, b0); fma2(acc[0][1], a0, b1); fma2(acc[0][2], a0, b2); fma2(acc[0][3], a0, b3);
            fma2(acc[1][0], a1, b0); fma2(acc[1][1], a1, b1); fma2(acc[1][2], a1, b2); fma2(acc[1][3], a1, b3);
            fma2(acc[2][0], a2, b0); fma2(acc[2][1], a2, b1); fma2(acc[2][2], a2, b2); fma2(acc[2][3], a2, b3);
            fma2(acc[3][0], a3, b0); fma2(acc[3][1], a3, b1); fma2(acc[3][2], a3, b2); fma2(acc[3][3], a3, b3);
        }

        if (kt < D / BK - 1) {
            float* An = As + (s ^ 1) * ASTRIDE;
            float* Bn = Bs + (s ^ 1) * BSTRIDE;
#pragma unroll
            for (int g = 0; g < 4; ++g) {
                const int m = ar + g * 32;
                An[(ac * 4 + 0) * PADA + m] = ra[g].x;
                An[(ac * 4 + 1) * PADA + m] = ra[g].y;
                An[(ac * 4 + 2) * PADA + m] = ra[g].z;
                An[(ac * 4 + 3) * PADA + m] = ra[g].w;
            }
#pragma unroll
            for (int g = 0; g < 2; ++g) {
                const int cc = bc + g * 4;
                Bn[(cc * 4 + 0) * PADB + br] = rb[g].x;
                Bn[(cc * 4 + 1) * PADB + br] = rb[g].y;
                Bn[(cc * 4 + 2) * PADB + br] = rb[g].z;
                Bn[(cc * 4 + 3) * PADB + br] = rb[g].w;
            }
        }
        __syncthreads();
    }

#pragma unroll
    for (int i = 0; i < 4; ++i) {
        float lo[4], hi[4];
#pragma unroll
        for (int j = 0; j < 4; ++j) unpack2(acc[i][j], lo[j], hi[j]);
        const int m = Mb + m0 + 2 * i;
        const int b0i = m >> 9, t0i = m & 511;
        const int b1i = (m + 1) >> 9, t1i = (m + 1) & 511;
        *(float4*)&g_ext[((size_t)t0i * BATCH + b0i) * D + Nb + n0] = make_float4(lo[0], lo[1], lo[2], lo[3]);
        *(float4*)&g_ext[((size_t)t1i * BATCH + b1i) * D + Nb + n0] = make_float4(hi[0], hi[1], hi[2], hi[3]);
    }
}

// ---------------- Phase B: persistent recurrence, dual-k-pair-packed FMA loop ----------
// 256 threads, 8 warps, 1 CTA/SM. Warp w = k-slice [128w,+128). Lane (mi=lane>>3,
// ni=lane&7): m rows {mi+4r}, n cols {ni+8j}, acc[4][4] k-pair-packed ULLs
// (lo=even-k sum, hi=odd-k sum; fold at epilogue). W in smem [n][k] row-major
// (stride 1028). Per 4k: 4 a-LDS.128 + 4 w-LDS.128 + 32 FFMA2 — ZERO MOVs,
// provably conflict-free banks -> compute is FMA-pipe-bound (4096 cyc/step/SM).
// Dataflow = R12: per-m-group 32-CTA counter barrier, single 64KB bulk copy into
// sT, epilogue writes relu(sum)+ext[t+1] into the combined ping-pong buffer.
#define NTILE 32
#define MTILE 16
#define WROWS 1028
#define WS_FLOATS (NTILE * WROWS)            // 32896
#define ST_FLOATS (MTILE * WROWS)            // 16448
#define REDW 544                              // 16 m * 34
#define RED_FLOATS (8 * REDW)                 // 4352
#define OFF_MBAR ((WS_FLOATS + ST_FLOATS + RED_FLOATS) * 4)
#define PERS_SMEM (OFF_MBAR + 16)             // 214800 B
#define TILE_BYTES (MTILE * D * 4)            // 65536

__global__ __launch_bounds__(256, 1) void rnn_persistent(const float* __restrict__ Wr) {
    extern __shared__ float sm[];
    float* Wsm = sm;                           // [32 n][1028]
    float* sT  = sm + WS_FLOATS;               // [16 m][1028]
    float* red = sm + WS_FLOATS + ST_FLOATS;   // [8 w][16 m * 34]

    const int tid  = threadIdx.x;
    const int w    = tid >> 5;
    const int lane = tid & 31;
    const int mi   = lane >> 3;                // 0..3
    const int ni   = lane & 7;                 // 0..7
    const int Nb = blockIdx.x * NTILE;
    const int Mb = blockIdx.y * MTILE;
    unsigned* bar = &g_bars[blockIdx.y * 32];

    const uint32_t mbar = smem_u32(sm) + OFF_MBAR;
    const uint32_t sT_a = smem_u32(sT);

    // reduce/epilogue mapping: thread -> (m row, n-pair)
    const int om = tid >> 4, op = tid & 15;

    // ---- stage Wsm[n][k] once (straight row copy, no transpose) ----
    {
        const int n = tid >> 3, c = tid & 7;
        const float4* src = (const float4*)(Wr + (size_t)(Nb + n) * D + c * 128);
        float4* dst = (float4*)(Wsm + (size_t)n * WROWS + c * 128);
#pragma unroll
        for (int j = 0; j < 32; ++j) dst[j] = __ldg(src + j);
    }
    if (tid == 0) {
        asm volatile("mbarrier.init.shared.b64 [%0], %1;" :: "r"(mbar), "r"(1) : "memory");
    }
    __syncthreads();

    for (int t = 0; t < TLEN; ++t) {
        // ---- prefetch ext[t+1] pair for this thread's outputs ----
        float2 e = make_float2(0.f, 0.f);
        if (t + 1 < TLEN)
            e = __ldg((const float2*)&g_ext[(size_t)(t + 1) * (BATCH * D) + (size_t)(Mb + om) * D + Nb + 2 * op]);

        // ---- barrier: all 32 producer CTAs of this m-group finished step t-1 ----
        if (t > 0) {
            if (tid == 0) {
                const unsigned target = 32u * (unsigned)t;
                unsigned v;
                do {
                    asm volatile("ld.acquire.gpu.u32 %0, [%1];" : "=r"(v) : "l"(bar));
                } while (v < target);
            }
            __syncthreads();
        }

        // ---- one 64KB bulk copy into sT (16 rows x 4KB) ----
        if (tid == 0) {
            const float* src = (t == 0) ? (g_ext + (size_t)Mb * D)
                                        : (g_sbuf[t & 1] + (size_t)Mb * D);
            asm volatile("mbarrier.arrive.expect_tx.shared.b64 _, [%0], %1;"
                         :: "r"(mbar), "r"(TILE_BYTES) : "memory");
#pragma unroll
            for (int m = 0; m < MTILE; ++m) {
                asm volatile("cp.async.bulk.shared::cta.global.mbarrier::complete_tx::bytes [%0], [%1], %2, [%3];"
                             :: "r"(sT_a + (uint32_t)(m * WROWS) * 4u),
                                "l"(src + (size_t)m * D), "r"(4096), "r"(mbar) : "memory");
            }
        }
        {
            const uint32_t parity = (uint32_t)(t & 1);
            uint32_t done;
            do {
                asm volatile(
                    "{\n\t.reg .pred p;\n\t"
                    "mbarrier.try_wait.parity.acquire.cta.shared::cta.b64 p, [%1], %2, 0x989680;\n\t"
                    "selp.b32 %0, 1, 0, p;\n\t}"
                    : "=r"(done) : "r"(mbar), "r"(parity) : "memory");
            } while (!done);
        }

        // ---- compute: acc[4 m][4 n] dual-k-pair-packed over this warp's 128-k ----
        ULL acc[4][4];
#pragma unroll
        for (int r = 0; r < 4; ++r)
#pragma unroll
            for (int j = 0; j < 4; ++j) acc[r][j] = 0ULL;

        const float* aB = sT + (size_t)mi * WROWS + w * 128;
        const float* wB = Wsm + (size_t)ni * WROWS + w * 128;

#pragma unroll 8
        for (int q = 0; q < 32; ++q) {
            const int k = 4 * q;
            ulonglong2 av[4], wv[4];
#pragma unroll
            for (int r = 0; r < 4; ++r)
                av[r] = *(const ulonglong2*)(aB + (size_t)r * (4 * WROWS) + k);
#pragma unroll
            for (int j = 0; j < 4; ++j)
                wv[j] = *(const ulonglong2*)(wB + (size_t)j * (8 * WROWS) + k);
#pragma unroll
            for (int r = 0; r < 4; ++r)
#pragma unroll
                for (int j = 0; j < 4; ++j) {
                    fma2(acc[r][j], av[r].x, wv[j].x);
                    fma2(acc[r][j], av[r].y, wv[j].y);
                }
        }

        // ---- fold k-parity, store per-warp partial floats ----
        {
            float* rw = red + w * REDW;
#pragma unroll
            for (int r = 0; r < 4; ++r)
#pragma unroll
                for (int j = 0; j < 4; ++j) {
                    float lo, hi;
                    unpack2(acc[r][j], lo, hi);
                    rw[(mi + 4 * r) * 34 + ni + 8 * j] = lo + hi;
                }
        }
        __syncthreads();

        // ---- reduce over 8 warps, ReLU, fuse ext[t+1], write combined buffer ----
        {
            float s0 = 0.f, s1 = 0.f;
#pragma unroll
            for (int g = 0; g < 8; ++g) {
                float2 v = *(const float2*)&red[g * REDW + om * 34 + 2 * op];
                s0 += v.x; s1 += v.y;
            }
            float v0 = fmaxf(s0, 0.f);
            float v1 = fmaxf(s1, 0.f);
            if (t + 1 < TLEN) { v0 += e.x; v1 += e.y; }
            float* sout = g_sbuf[(t + 1) & 1];
            __stcg((float2*)&sout[(size_t)(Mb + om) * D + Nb + 2 * op], make_float2(v0, v1));
        }
        __syncthreads();   // red reads + STGs done before signal / sT reuse

        if (tid == 0) {
            __threadfence();
            atomicAdd(bar, 1u);
        }
    }
}

// ---------------- final: out[:,0,:] = final state (g_sbuf[0], TLEN even) ----------------
__global__ void final_copy_kernel(float* __restrict__ out) {
    const int i = blockIdx.x * blockDim.x + threadIdx.x;   // < 65536
    const int b = i >> 10, o = i & 1023;
    out[(size_t)b * (TLEN * D) + o] = g_sbuf[0][i];
}

// ---------------- launch ----------------
extern "C" void kernel_launch(void* const* d_in, const int* in_sizes, int n_in,
                              void* d_out, int out_size) {
    const float* x     = (const float*)d_in[0];
    const float* W_in  = (const float*)d_in[1];
    const float* W_rec = (const float*)d_in[2];
    float* out = (float*)d_out;

    cudaFuncSetAttribute(rnn_persistent, cudaFuncAttributeMaxDynamicSharedMemorySize, PERS_SMEM);
    cudaFuncSetAttribute(ext_gemm_kernel, cudaFuncAttributeMaxDynamicSharedMemorySize, EXT_SMEM);

    // zero output (poisoned by harness) + barrier counters
    zero4_kernel<<<(BATCH * TLEN * D / 4 + 255) / 256, 256>>>((float4*)out, BATCH * TLEN * D / 4);
    zero_misc_kernel<<<1, 128>>>();

    // Phase A: input projections for all timesteps (ext layout [t][b][o])
    ext_gemm_kernel<<<dim3(D / BN, (BATCH * TLEN) / BM), 256, EXT_SMEM>>>(x, W_in);

    // Phase B: full recurrence in one persistent kernel
    rnn_persistent<<<dim3(D / NTILE, BATCH / MTILE), 256, PERS_SMEM>>>(W_rec);

    // write final state into out[:,0,:]
    final_copy_kernel<<<(BATCH * D) / 256, 256>>>(out);
}

// round 17
// speedup vs baseline: 1.8301x; 1.0046x over previous
#include <cuda_runtime.h>
#include <cstdint>

#define BATCH 64
#define TLEN  512
#define D     1024

// ---------------- scratch (device globals: no allocations allowed) ----------------
__device__ float g_ext[(size_t)TLEN * BATCH * D];   // 128 MB, layout [t][b][o]
__device__ float g_sbuf[2][BATCH * D];              // ping-pong: state + ext[t] combined
__device__ unsigned g_hbar[8 * 32];                  // [m-group][half] counters, 128B apart

typedef unsigned long long ULL;

// ---------------- packed f32x2 helpers (sm_103a FFMA2 path) ----------------
static __device__ __forceinline__ ULL pack_dup(float w) {
    ULL r;
    asm("mov.b64 %0, {%1, %1};" : "=l"(r) : "f"(w));
    return r;
}
static __device__ __forceinline__ void fma2(ULL& d, ULL a, ULL b) {
    asm("fma.rn.f32x2 %0, %1, %2, %0;" : "+l"(d) : "l"(a), "l"(b));
}
static __device__ __forceinline__ void unpack2(ULL v, float& lo, float& hi) {
    asm("mov.b64 {%0, %1}, %2;" : "=f"(lo), "=f"(hi) : "l"(v));
}
static __device__ __forceinline__ uint32_t smem_u32(const void* p) {
    uint32_t a;
    asm("{ .reg .u64 t; cvta.to.shared.u64 t, %1; cvt.u32.u64 %0, t; }" : "=r"(a) : "l"(p));
    return a;
}
static __device__ __forceinline__ void mbar_wait(uint32_t mb, uint32_t parity) {
    uint32_t done;
    do {
        asm volatile(
            "{\n\t.reg .pred p;\n\t"
            "mbarrier.try_wait.parity.acquire.cta.shared::cta.b64 p, [%1], %2, 0x989680;\n\t"
            "selp.b32 %0, 1, 0, p;\n\t}"
            : "=r"(done) : "r"(mb), "r"(parity) : "memory");
    } while (!done);
}

// ---------------- trivial zero kernels ----------------
__global__ void zero4_kernel(float4* __restrict__ p, int n4) {
    int i = blockIdx.x * blockDim.x + threadIdx.x;
    if (i < n4) p[i] = make_float4(0.f, 0.f, 0.f, 0.f);
}
__global__ void zero_misc_kernel() {
    int i = blockIdx.x * blockDim.x + threadIdx.x;
    if (i < 8 * 32) g_hbar[i] = 0u;
}

// ---------------- Phase A: ext[t][b][o] = sum_k x[m][k] * W_in[o][k], m=b*512+t --------
#define BM 128
#define BN 64
#define BK 32
#define PADA 134
#define PADB 68
#define ASTRIDE (BK * PADA)
#define BSTRIDE (BK * PADB)
#define EXT_SMEM ((2 * ASTRIDE + 2 * BSTRIDE) * 4)   // 51712 B

__global__ __launch_bounds__(256, 2) void ext_gemm_kernel(const float* __restrict__ X,
                                                          const float* __restrict__ Win) {
    extern __shared__ float esm[];
    float* As = esm;
    float* Bs = esm + 2 * ASTRIDE;

    const int tid = threadIdx.x;
    const int Mb = blockIdx.y * BM;
    const int Nb = blockIdx.x * BN;
    const int ty = tid >> 4, tx = tid & 15;
    const int m0 = ty * 8, n0 = tx * 4;

    ULL acc[4][4];
#pragma unroll
    for (int i = 0; i < 4; ++i)
#pragma unroll
        for (int j = 0; j < 4; ++j) acc[i][j] = 0ULL;

    const int ar = tid >> 3, ac = tid & 7;
    const int br = tid >> 2, bc = tid & 3;

    float4 ra[4], rb[2];
#pragma unroll
    for (int g = 0; g < 4; ++g)
        ra[g] = *(const float4*)&X[(size_t)(Mb + ar + g * 32) * D + ac * 4];
#pragma unroll
    for (int g = 0; g < 2; ++g)
        rb[g] = *(const float4*)&Win[(size_t)(Nb + br) * D + (bc + g * 4) * 4];
    {
#pragma unroll
        for (int g = 0; g < 4; ++g) {
            const int m = ar + g * 32;
            As[(ac * 4 + 0) * PADA + m] = ra[g].x;
            As[(ac * 4 + 1) * PADA + m] = ra[g].y;
            As[(ac * 4 + 2) * PADA + m] = ra[g].z;
            As[(ac * 4 + 3) * PADA + m] = ra[g].w;
        }
#pragma unroll
        for (int g = 0; g < 2; ++g) {
            const int cc = bc + g * 4;
            Bs[(cc * 4 + 0) * PADB + br] = rb[g].x;
            Bs[(cc * 4 + 1) * PADB + br] = rb[g].y;
            Bs[(cc * 4 + 2) * PADB + br] = rb[g].z;
            Bs[(cc * 4 + 3) * PADB + br] = rb[g].w;
        }
    }
    __syncthreads();

    for (int kt = 0; kt < D / BK; ++kt) {
        const int s = kt & 1;
        const float* Ac = As + s * ASTRIDE;
        const float* Bc = Bs + s * BSTRIDE;

        if (kt < D / BK - 1) {
            const int k0 = (kt + 1) * BK;
#pragma unroll
            for (int g = 0; g < 4; ++g)
                ra[g] = *(const float4*)&X[(size_t)(Mb + ar + g * 32) * D + k0 + ac * 4];
#pragma unroll
            for (int g = 0; g < 2; ++g)
                rb[g] = *(const float4*)&Win[(size_t)(Nb + br) * D + k0 + (bc + g * 4) * 4];
        }

#pragma unroll
        for (int kk = 0; kk < BK; ++kk) {
            const float* asr = &Ac[kk * PADA + m0];
            ULL a0 = *(const ULL*)(asr + 0);
            ULL a1 = *(const ULL*)(asr + 2);
            ULL a2 = *(const ULL*)(asr + 4);
            ULL a3 = *(const ULL*)(asr + 6);
            float4 bv = *(const float4*)&Bc[kk * PADB + n0];
            ULL b0 = pack_dup(bv.x);
            ULL b1 = pack_dup(bv.y);
            ULL b2 = pack_dup(bv.z);
            ULL b3 = pack_dup(bv.w);
            fma2(acc[0][0], a0, b0); fma2(acc[0][1], a0, b1); fma2(acc[0][2], a0, b2); fma2(acc[0][3], a0, b3);
            fma2(acc[1][0], a1, b0); fma2(acc[1][1], a1, b1); fma2(acc[1][2], a1, b2); fma2(acc[1][3], a1, b3);
            fma2(acc[2][0], a2, b0); fma2(acc[2][1], a2, b1); fma2(acc[2][2], a2, b2); fma2(acc[2][3], a2, b3);
            fma2(acc[3][0], a3, b0); fma2(acc[3][1], a3, b1); fma2(acc[3][2], a3, b2); fma2(acc[3][3], a3, b3);
        }

        if (kt < D / BK - 1) {
            float* An = As + (s ^ 1) * ASTRIDE;
            float* Bn = Bs + (s ^ 1) * BSTRIDE;
#pragma unroll
            for (int g = 0; g < 4; ++g) {
                const int m = ar + g * 32;
                An[(ac * 4 + 0) * PADA + m] = ra[g].x;
                An[(ac * 4 + 1) * PADA + m] = ra[g].y;
                An[(ac * 4 + 2) * PADA + m] = ra[g].z;
                An[(ac * 4 + 3) * PADA + m] = ra[g].w;
            }
#pragma unroll
            for (int g = 0; g < 2; ++g) {
                const int cc = bc + g * 4;
                Bn[(cc * 4 + 0) * PADB + br] = rb[g].x;
                Bn[(cc * 4 + 1) * PADB + br] = rb[g].y;
                Bn[(cc * 4 + 2) * PADB + br] = rb[g].z;
                Bn[(cc * 4 + 3) * PADB + br] = rb[g].w;
            }
        }
        __syncthreads();
    }

#pragma unroll
    for (int i = 0; i < 4; ++i) {
        float lo[4], hi[4];
#pragma unroll
        for (int j = 0; j < 4; ++j) unpack2(acc[i][j], lo[j], hi[j]);
        const int m = Mb + m0 + 2 * i;
        const int b0i = m >> 9, t0i = m & 511;
        const int b1i = (m + 1) >> 9, t1i = (m + 1) & 511;
        *(float4*)&g_ext[((size_t)t0i * BATCH + b0i) * D + Nb + n0] = make_float4(lo[0], lo[1], lo[2], lo[3]);
        *(float4*)&g_ext[((size_t)t1i * BATCH + b1i) * D + Nb + n0] = make_float4(hi[0], hi[1], hi[2], hi[3]);
    }
}

// ---------------- Phase B: persistent recurrence, DMA-warp + m-half pipeline ----------
// 288 threads: warps 0-7 compute, warp 8 = DMA agent. Rows split into two independent
// 8-row sub-recurrences (halves). DMA warp polls producer counters and issues bulk
// copies for half h+1 while compute warps work on half h — detection + copy latency
// hide inside the other half's compute. Compute tile per half: warp = 128-k slice,
// lane (mi=lane>>3, ni=lane&7): rows {mi, mi+4}, n cols {ni+8j}; acc[2][4] dual-k-pair
// packed (zero MOVs, conflict-free). Reduce + fused relu+ext epilogue among 256
// compute threads via named barrier (DMA warp never joins).
#define NTILE 32
#define MTILE 16
#define WROWS 1028
#define WS_FLOATS (NTILE * WROWS)             // 32896
#define ST_OFF WS_FLOATS
#define ST_FLOATS (MTILE * WROWS)             // 16448 (two 8-row halves)
#define RED_OFF (ST_OFF + ST_FLOATS)
#define REDW 288                               // 8 rows * 36 (2-way max on stores)
#define RED_FLOATS (8 * REDW)                  // 2304
#define OFF_MBAR ((RED_OFF + RED_FLOATS) * 4)
#define PERS_SMEM (OFF_MBAR + 64)              // full[2] @ +0,+8; empty[2] @ +16,+24
#define HALF_BYTES (8 * D * 4)                 // 32768

__global__ __launch_bounds__(288, 1) void rnn_persistent(const float* __restrict__ Wr) {
    extern __shared__ float sm[];
    float* Wsm = sm;                            // [32 n][1028]
    float* sT  = sm + ST_OFF;                   // [16 m][1028]: half h at +h*8*1028
    float* red = sm + RED_OFF;                  // [8 w][8 m * 36]

    const int tid  = threadIdx.x;
    const int Nb = blockIdx.x * NTILE;
    const int Mb = blockIdx.y * MTILE;

    const uint32_t mbar  = smem_u32(sm) + OFF_MBAR;    // full[h]=+8h, empty[h]=+16+8h
    const uint32_t sT_a  = smem_u32(sT);

    // ---- stage Wsm[n][k] once (288 threads; straight row copy) ----
    {
        for (int idx = tid; idx < 32 * 8; idx += 288) {
            const int n = idx >> 3, c = idx & 7;
            const float4* src = (const float4*)(Wr + (size_t)(Nb + n) * D + c * 128);
            float4* dst = (float4*)(Wsm + (size_t)n * WROWS + c * 128);
#pragma unroll
            for (int j = 0; j < 32; ++j) dst[j] = __ldg(src + j);
        }
    }
    if (tid < 2) {
        asm volatile("mbarrier.init.shared.b64 [%0], %1;"
                     :: "r"(mbar + 8u * (uint32_t)tid), "r"(1) : "memory");      // full
        asm volatile("mbarrier.init.shared.b64 [%0], %1;"
                     :: "r"(mbar + 16u + 8u * (uint32_t)tid), "r"(8) : "memory"); // empty
    }
    __syncthreads();

    if (tid >= 256) {
        // ================= DMA warp (lane 0 only) =================
        if (tid == 256) {
            // prologue: both halves of step 0 from ext[0] (state0 = 0)
#pragma unroll
            for (int h = 0; h < 2; ++h) {
                const float* src = g_ext + (size_t)(Mb + 8 * h) * D;
                const uint32_t fb = mbar + 8u * (uint32_t)h;
                asm volatile("mbarrier.arrive.expect_tx.shared.b64 _, [%0], %1;"
                             :: "r"(fb), "r"(HALF_BYTES) : "memory");
#pragma unroll
                for (int m = 0; m < 8; ++m) {
                    asm volatile("cp.async.bulk.shared::cta.global.mbarrier::complete_tx::bytes [%0], [%1], %2, [%3];"
                                 :: "r"(sT_a + (uint32_t)((h * 8 + m) * WROWS) * 4u),
                                    "l"(src + (size_t)m * D), "r"(4096), "r"(fb) : "memory");
                }
            }
            // steady state: copy (t, h) after compute released buffer and producers signaled
            for (int t = 1; t < TLEN; ++t) {
                for (int h = 0; h < 2; ++h) {
                    mbar_wait(mbar + 16u + 8u * (uint32_t)h, (uint32_t)((t - 1) & 1));
                    unsigned* ctr = &g_hbar[(blockIdx.y * 2 + h) * 32];
                    const unsigned target = 32u * (unsigned)t;
                    unsigned v;
                    do {
                        asm volatile("ld.acquire.gpu.u32 %0, [%1];" : "=r"(v) : "l"(ctr));
                        if (v < target) __nanosleep(32);
                    } while (v < target);
                    const float* src = g_sbuf[t & 1] + (size_t)(Mb + 8 * h) * D;
                    const uint32_t fb = mbar + 8u * (uint32_t)h;
                    asm volatile("mbarrier.arrive.expect_tx.shared.b64 _, [%0], %1;"
                                 :: "r"(fb), "r"(HALF_BYTES) : "memory");
#pragma unroll
                    for (int m = 0; m < 8; ++m) {
                        asm volatile("cp.async.bulk.shared::cta.global.mbarrier::complete_tx::bytes [%0], [%1], %2, [%3];"
                                     :: "r"(sT_a + (uint32_t)((h * 8 + m) * WROWS) * 4u),
                                        "l"(src + (size_t)m * D), "r"(4096), "r"(fb) : "memory");
                    }
                }
            }
        }
        return;
    }

    // ================= compute warps (tid < 256) =================
    const int w    = tid >> 5;
    const int lane = tid & 31;
    const int mi   = lane >> 3;                 // 0..3: rows {mi, mi+4}
    const int ni   = lane & 7;                  // n cols {ni + 8j}
    const int om = tid >> 5, on = tid & 31;     // reduce/epilogue: 1 output/thread

    for (int t = 0; t < TLEN; ++t) {
#pragma unroll
        for (int h = 0; h < 2; ++h) {
            // prefetch ext[t+1] for this thread's output (hidden by wait+compute)
            float e = 0.f;
            if (t + 1 < TLEN)
                e = __ldg(&g_ext[(size_t)(t + 1) * (BATCH * D) + (size_t)(Mb + 8 * h + om) * D + Nb + on]);

            // wait for this half's input tile
            mbar_wait(mbar + 8u * (uint32_t)h, (uint32_t)(t & 1));

            // compute acc[2][4], dual-k-pair packed, this warp's 128-k slice
            ULL acc[2][4];
#pragma unroll
            for (int r = 0; r < 2; ++r)
#pragma unroll
                for (int j = 0; j < 4; ++j) acc[r][j] = 0ULL;

            const float* aB = sT + (size_t)(h * 8 + mi) * WROWS + w * 128;
            const float* wB = Wsm + (size_t)ni * WROWS + w * 128;
#pragma unroll 8
            for (int q = 0; q < 32; ++q) {
                const int k = 4 * q;
                ulonglong2 av0 = *(const ulonglong2*)(aB + k);
                ulonglong2 av1 = *(const ulonglong2*)(aB + 4 * WROWS + k);
                ulonglong2 wv[4];
#pragma unroll
                for (int j = 0; j < 4; ++j)
                    wv[j] = *(const ulonglong2*)(wB + (size_t)j * (8 * WROWS) + k);
#pragma unroll
                for (int j = 0; j < 4; ++j) {
                    fma2(acc[0][j], av0.x, wv[j].x);
                    fma2(acc[0][j], av0.y, wv[j].y);
                    fma2(acc[1][j], av1.x, wv[j].x);
                    fma2(acc[1][j], av1.y, wv[j].y);
                }
            }

            // release the buffer to the DMA warp (sT reads complete)
            if (lane == 0) {
                asm volatile("mbarrier.arrive.shared.b64 _, [%0];"
                             :: "r"(mbar + 16u + 8u * (uint32_t)h) : "memory");
            }

            // fold k-parity, store per-warp partials
            {
                float* rw = red + w * REDW;
#pragma unroll
                for (int r = 0; r < 2; ++r)
#pragma unroll
                    for (int j = 0; j < 4; ++j) {
                        float lo, hi;
                        unpack2(acc[r][j], lo, hi);
                        rw[(mi + 4 * r) * 36 + ni + 8 * j] = lo + hi;
                    }
            }
            asm volatile("bar.sync 1, 256;" ::: "memory");

            // reduce over 8 k-slices, ReLU, fuse ext[t+1], write combined buffer
            {
                float s = 0.f;
#pragma unroll
                for (int g = 0; g < 8; ++g) s += red[g * REDW + om * 36 + on];
                float v = fmaxf(s, 0.f);
                if (t + 1 < TLEN) v += e;
                __stcg(&g_sbuf[(t + 1) & 1][(size_t)(Mb + 8 * h + om) * D + Nb + on], v);
            }
            asm volatile("bar.sync 1, 256;" ::: "memory");

            // signal this half's production for step t
            if (tid == 0) {
                __threadfence();
                atomicAdd(&g_hbar[(blockIdx.y * 2 + h) * 32], 1u);
            }
        }
    }
}

// ---------------- final: out[:,0,:] = final state (g_sbuf[0], TLEN even) ----------------
__global__ void final_copy_kernel(float* __restrict__ out) {
    const int i = blockIdx.x * blockDim.x + threadIdx.x;   // < 65536
    const int b = i >> 10, o = i & 1023;
    out[(size_t)b * (TLEN * D) + o] = g_sbuf[0][i];
}

// ---------------- launch ----------------
extern "C" void kernel_launch(void* const* d_in, const int* in_sizes, int n_in,
                              void* d_out, int out_size) {
    const float* x     = (const float*)d_in[0];
    const float* W_in  = (const float*)d_in[1];
    const float* W_rec = (const float*)d_in[2];
    float* out = (float*)d_out;

    cudaFuncSetAttribute(rnn_persistent, cudaFuncAttributeMaxDynamicSharedMemorySize, PERS_SMEM);
    cudaFuncSetAttribute(ext_gemm_kernel, cudaFuncAttributeMaxDynamicSharedMemorySize, EXT_SMEM);

    // zero output (poisoned by harness) + dataflow counters
    zero4_kernel<<<(BATCH * TLEN * D / 4 + 255) / 256, 256>>>((float4*)out, BATCH * TLEN * D / 4);
    zero_misc_kernel<<<1, 256>>>();

    // Phase A: input projections for all timesteps (ext layout [t][b][o])
    ext_gemm_kernel<<<dim3(D / BN, (BATCH * TLEN) / BM), 256, EXT_SMEM>>>(x, W_in);

    // Phase B: full recurrence in one persistent kernel
    rnn_persistent<<<dim3(D / NTILE, BATCH / MTILE), 288, PERS_SMEM>>>(W_rec);

    // write final state into out[:,0,:]
    final_copy_kernel<<<(BATCH * D) / 256, 256>>>(out);
}